// round 1
// baseline (speedup 1.0000x reference)
#include <cuda_runtime.h>
#include <math.h>

#define T_TOK 2048
#define H_DIM 1024
#define F_DIM 4096
#define NEXP  4

#define BM 128
#define BN 128
#define BK 8
#define TM 8
#define TN 8
// 256 threads per GEMM block (16x16 thread grid, 8x8 micro-tile)

// -------- scratch (device globals: allocation-free) --------
__device__ int   g_cnt[NEXP];
__device__ int   g_off[NEXP + 1];
__device__ int   g_idx[NEXP * T_TOK];            // token ids per expert, compact
__device__ int   g_pos[T_TOK * NEXP];            // position of token t in expert e's list, -1 if not routed
__device__ float g_act[(size_t)T_TOK * 2 * F_DIM]; // compact [4096, F]  (64 MB)
__device__ float g_y  [(size_t)T_TOK * 2 * H_DIM]; // compact [4096, H]  (16 MB)

// -------- 1) routing lists (deterministic: sequential scan per expert) --------
__global__ void build_lists(const float* __restrict__ probs) {
    int e = threadIdx.x;
    if (e < NEXP) {
        int c = 0;
        for (int t = 0; t < T_TOK; ++t) {
            float p = probs[t * NEXP + e];
            if (p > 0.0f) {
                g_idx[e * T_TOK + c] = t;
                g_pos[t * NEXP + e]  = c;
                ++c;
            } else {
                g_pos[t * NEXP + e] = -1;
            }
        }
        g_cnt[e] = c;
    }
    __syncthreads();
    if (e == 0) {
        int acc = 0;
        for (int i = 0; i < NEXP; ++i) { g_off[i] = acc; acc += g_cnt[i]; }
        g_off[NEXP] = acc;
    }
}

// -------- 2) gathered SGEMM: A = gelu(X[idx] @ W1[e]),  K=H_DIM, N=F_DIM --------
__global__ __launch_bounds__(256) void gemm1(const float* __restrict__ X,
                                             const float* __restrict__ W1) {
    const int e   = blockIdx.z;
    const int cnt = g_cnt[e];
    const int rowBase = blockIdx.y * BM;
    if (rowBase >= cnt) return;
    const int off   = g_off[e];
    const int nBase = blockIdx.x * BN;
    const float* __restrict__ W = W1 + (size_t)e * H_DIM * F_DIM;

    __shared__ float As[BK][BM + 4];
    __shared__ float Bs[BK][BN];

    const int tid = threadIdx.x;
    const int tx = tid % 16, ty = tid / 16;

    // token ids for the 4 A-rows this thread loads each k-tile
    int tokA[4];
#pragma unroll
    for (int i = 0; i < 4; ++i) {
        int r  = i * 32 + (tid >> 3);
        int gr = rowBase + r;
        tokA[i] = (gr < cnt) ? g_idx[e * T_TOK + gr] : -1;
    }

    float acc[TM][TN];
#pragma unroll
    for (int i = 0; i < TM; ++i)
#pragma unroll
        for (int j = 0; j < TN; ++j) acc[i][j] = 0.0f;

    for (int k0 = 0; k0 < H_DIM; k0 += BK) {
#pragma unroll
        for (int i = 0; i < 4; ++i) {          // A tile (gathered, transposed store)
            int r = i * 32 + (tid >> 3);
            int k = tid & 7;
            float v = 0.0f;
            if (tokA[i] >= 0) v = X[(size_t)tokA[i] * H_DIM + k0 + k];
            As[k][r] = v;
        }
#pragma unroll
        for (int i = 0; i < 4; ++i) {          // B tile (coalesced along n)
            int k = i * 2 + (tid >> 7);
            int n = tid & 127;
            Bs[k][n] = W[(size_t)(k0 + k) * F_DIM + nBase + n];
        }
        __syncthreads();
#pragma unroll
        for (int k = 0; k < BK; ++k) {
            float a_frag[TM], b_frag[TN];
#pragma unroll
            for (int i = 0; i < TM; ++i) a_frag[i] = As[k][ty * TM + i];
#pragma unroll
            for (int j = 0; j < TN; ++j) b_frag[j] = Bs[k][tx * TN + j];
#pragma unroll
            for (int i = 0; i < TM; ++i)
#pragma unroll
                for (int j = 0; j < TN; ++j) acc[i][j] += a_frag[i] * b_frag[j];
        }
        __syncthreads();
    }

#pragma unroll
    for (int i = 0; i < TM; ++i) {
        int gr = rowBase + ty * TM + i;
        if (gr < cnt) {
            float* dst = g_act + (size_t)(off + gr) * F_DIM + nBase + tx * TN;
#pragma unroll
            for (int j = 0; j < TN; ++j) {
                float v = acc[i][j];
                dst[j] = 0.5f * v * (1.0f + erff(v * 0.70710678118654752f)); // exact gelu
            }
        }
    }
}

// -------- 3) SGEMM: Y = A @ W2[e],  K=F_DIM, N=H_DIM --------
__global__ __launch_bounds__(256) void gemm2(const float* __restrict__ W2) {
    const int e   = blockIdx.z;
    const int cnt = g_cnt[e];
    const int rowBase = blockIdx.y * BM;
    if (rowBase >= cnt) return;
    const int off   = g_off[e];
    const int nBase = blockIdx.x * BN;
    const float* __restrict__ W = W2 + (size_t)e * F_DIM * H_DIM;

    __shared__ float As[BK][BM + 4];
    __shared__ float Bs[BK][BN];

    const int tid = threadIdx.x;
    const int tx = tid % 16, ty = tid / 16;

    float acc[TM][TN];
#pragma unroll
    for (int i = 0; i < TM; ++i)
#pragma unroll
        for (int j = 0; j < TN; ++j) acc[i][j] = 0.0f;

    for (int k0 = 0; k0 < F_DIM; k0 += BK) {
#pragma unroll
        for (int i = 0; i < 4; ++i) {          // A tile (compact rows)
            int r  = i * 32 + (tid >> 3);
            int k  = tid & 7;
            int gr = rowBase + r;
            As[k][r] = (gr < cnt) ? g_act[(size_t)(off + gr) * F_DIM + k0 + k] : 0.0f;
        }
#pragma unroll
        for (int i = 0; i < 4; ++i) {          // B tile
            int k = i * 2 + (tid >> 7);
            int n = tid & 127;
            Bs[k][n] = W[(size_t)(k0 + k) * H_DIM + nBase + n];
        }
        __syncthreads();
#pragma unroll
        for (int k = 0; k < BK; ++k) {
            float a_frag[TM], b_frag[TN];
#pragma unroll
            for (int i = 0; i < TM; ++i) a_frag[i] = As[k][ty * TM + i];
#pragma unroll
            for (int j = 0; j < TN; ++j) b_frag[j] = Bs[k][tx * TN + j];
#pragma unroll
            for (int i = 0; i < TM; ++i)
#pragma unroll
                for (int j = 0; j < TN; ++j) acc[i][j] += a_frag[i] * b_frag[j];
        }
        __syncthreads();
    }

#pragma unroll
    for (int i = 0; i < TM; ++i) {
        int gr = rowBase + ty * TM + i;
        if (gr < cnt) {
            float* dst = g_y + (size_t)(off + gr) * H_DIM + nBase + tx * TN;
#pragma unroll
            for (int j = 0; j < TN; ++j) dst[j] = acc[i][j];
        }
    }
}

// -------- 4) deterministic combine: out = residual + sum_e p * Y --------
__global__ __launch_bounds__(256) void combine(const float* __restrict__ probs,
                                               const float* __restrict__ resid,
                                               float* __restrict__ out) {
    const int t  = blockIdx.x;
    const int h4 = threadIdx.x;                      // 256 threads * float4 = 1024 floats
    float4 r = reinterpret_cast<const float4*>(resid + (size_t)t * H_DIM)[h4];
#pragma unroll
    for (int e = 0; e < NEXP; ++e) {
        int pos = g_pos[t * NEXP + e];
        if (pos >= 0) {
            float p = probs[t * NEXP + e];
            const float4* yy = reinterpret_cast<const float4*>(
                g_y + (size_t)(g_off[e] + pos) * H_DIM);
            float4 v = yy[h4];
            r.x += p * v.x; r.y += p * v.y; r.z += p * v.z; r.w += p * v.w;
        }
    }
    reinterpret_cast<float4*>(out + (size_t)t * H_DIM)[h4] = r;
}

extern "C" void kernel_launch(void* const* d_in, const int* in_sizes, int n_in,
                              void* d_out, int out_size) {
    const float* hidden = (const float*)d_in[0];   // [S,B,H] = [T,H]
    const float* resid  = (const float*)d_in[1];   // [T,H]
    const float* probs  = (const float*)d_in[2];   // [T,E]
    // d_in[3] = routing_map (bool) — unused; probs>0 encodes routing exactly
    const float* w1     = (const float*)d_in[4];   // [E,H,F]
    const float* w2     = (const float*)d_in[5];   // [E,F,H]
    float* out = (float*)d_out;

    build_lists<<<1, 32>>>(probs);

    dim3 g1(F_DIM / BN, T_TOK / BM, NEXP);         // worst-case M per expert; early-exit tiles
    gemm1<<<g1, 256>>>(hidden, w1);

    dim3 g2(H_DIM / BN, T_TOK / BM, NEXP);
    gemm2<<<g2, 256>>>(w2);

    combine<<<T_TOK, 256>>>(probs, resid, out);
}

// round 7
// speedup vs baseline: 1.4933x; 1.4933x over previous
#include <cuda_runtime.h>
#include <cuda_bf16.h>
#include <mma.h>
#include <math.h>
#include <stdint.h>

using namespace nvcuda;

#define T_TOK 2048
#define H_DIM 1024
#define F_DIM 4096
#define NEXP  4

#define BM 128
#define BN 128
#define BK 16
#define LDA 24            // A tile ld (elems): 48 B rows
#define LDB 136           // B tile ld (elems): 272 B rows
// SMEM bytes: sAh 0..6144, sAl 6144..12288, sBh 12288..16640, sBl 16640..20992

__device__ __forceinline__ uint32_t pack_bf2(__nv_bfloat16 a, __nv_bfloat16 b) {
    __nv_bfloat162 t; t.x = a; t.y = b;
    return *reinterpret_cast<uint32_t*>(&t);
}
__device__ __forceinline__ float gelu_f(float v) {
    return 0.5f * v * (1.0f + erff(v * 0.70710678118654752440f));
}
// split 8 fp32 -> 8 bf16 hi + 8 bf16 lo, packed as uint4 each
__device__ __forceinline__ void split8(const float* r, uint4& hv, uint4& lv) {
    uint32_t h[4], l[4];
#pragma unroll
    for (int u = 0; u < 4; ++u) {
        float a = r[u * 2], b = r[u * 2 + 1];
        __nv_bfloat16 ha = __float2bfloat16_rn(a), hb = __float2bfloat16_rn(b);
        h[u] = pack_bf2(ha, hb);
        l[u] = pack_bf2(__float2bfloat16_rn(a - __bfloat162float(ha)),
                        __float2bfloat16_rn(b - __bfloat162float(hb)));
    }
    hv = make_uint4(h[0], h[1], h[2], h[3]);
    lv = make_uint4(l[0], l[1], l[2], l[3]);
}

// ============================ scratch (round-1 footprint) ============================
__device__ float g_act[(size_t)T_TOK * 2 * F_DIM];   // compact fp32 [4096][F]
__device__ float g_y[(size_t)T_TOK * 2 * H_DIM];     // compact fp32 [4096][H]
__device__ int g_cnt[NEXP];
__device__ int g_off[NEXP + 1];
__device__ int g_idx[NEXP * T_TOK];
__device__ int g_pos[T_TOK * NEXP];

// ============================ routing (verbatim round 1) ============================
__global__ void build_lists(const float* __restrict__ probs) {
    int e = threadIdx.x;
    if (e < NEXP) {
        int c = 0;
        for (int t = 0; t < T_TOK; ++t) {
            float p = probs[t * NEXP + e];
            if (p > 0.0f) {
                g_idx[e * T_TOK + c] = t;
                g_pos[t * NEXP + e]  = c;
                ++c;
            } else {
                g_pos[t * NEXP + e] = -1;
            }
        }
        g_cnt[e] = c;
    }
    __syncthreads();
    if (e == 0) {
        int acc = 0;
        for (int i = 0; i < NEXP; ++i) { g_off[i] = acc; acc += g_cnt[i]; }
        g_off[NEXP] = acc;
    }
}

// ============================ wmma bf16x3 GEMM, fp32 operands loaded directly ============================
// 8 warps = 4(m) x 2(n); warp tile 32m x 64n; wmma 16x16x16.
// A: gathered fp32 rows (X via g_idx for G1; g_act compact for G2), split in-register.
// B: original weights [e][K][N] row-major, consumed as wmma matrix_b row_major. No transpose.
template <bool G1>
__global__ __launch_bounds__(256, 1) void gemm_wmma(const float* __restrict__ X,
                                                    const float* __restrict__ W) {
    __shared__ __align__(16) char smem[20992];
    __nv_bfloat16* sAh = reinterpret_cast<__nv_bfloat16*>(smem);
    __nv_bfloat16* sAl = reinterpret_cast<__nv_bfloat16*>(smem + 6144);
    __nv_bfloat16* sBh = reinterpret_cast<__nv_bfloat16*>(smem + 12288);
    __nv_bfloat16* sBl = reinterpret_cast<__nv_bfloat16*>(smem + 16640);

    const int e = blockIdx.z, mt = blockIdx.y, nt = blockIdx.x;
    const int cnt = g_cnt[e];
    const int rowBase = mt * BM;
    if (rowBase >= cnt) return;
    const int off = g_off[e];
    constexpr int K = G1 ? H_DIM : F_DIM;
    constexpr int N = G1 ? F_DIM : H_DIM;
    constexpr int KIT = K / BK;

    const int tid = threadIdx.x, lane = tid & 31, wid = tid >> 5;
    const int wm = wid & 3, wn = wid >> 2;

    // ---- A: 2 threads per row, 8 fp32 each ----
    const int lrow = tid >> 1, lhalf = tid & 1;
    const float* Asrc;
    {
        int gr = rowBase + lrow;
        int cr = gr < cnt ? gr : cnt - 1;          // clamp; masked at epilogue
        if (G1) Asrc = X + (size_t)g_idx[e * T_TOK + cr] * H_DIM;
        else    Asrc = g_act + (size_t)(off + cr) * F_DIM;
    }
    // ---- B: 16 threads per k-row, 8 fp32 each; W is [e][K][N] row-major ----
    const int kq = tid >> 4, cq = tid & 15;
    const float* Bsrc = W + (size_t)e * K * N + nt * BN + cq * 8;

    float ra[8], rb[8];
    auto loadA = [&](int k0) {
        float4 v0 = *reinterpret_cast<const float4*>(Asrc + k0 + lhalf * 8);
        float4 v1 = *reinterpret_cast<const float4*>(Asrc + k0 + lhalf * 8 + 4);
        ra[0] = v0.x; ra[1] = v0.y; ra[2] = v0.z; ra[3] = v0.w;
        ra[4] = v1.x; ra[5] = v1.y; ra[6] = v1.z; ra[7] = v1.w;
    };
    auto loadB = [&](int k0) {
        const float* p = Bsrc + (size_t)(k0 + kq) * N;
        float4 v0 = *reinterpret_cast<const float4*>(p);
        float4 v1 = *reinterpret_cast<const float4*>(p + 4);
        rb[0] = v0.x; rb[1] = v0.y; rb[2] = v0.z; rb[3] = v0.w;
        rb[4] = v1.x; rb[5] = v1.y; rb[6] = v1.z; rb[7] = v1.w;
    };

    wmma::fragment<wmma::accumulator, 16, 16, 16, float> facc[2][4];
#pragma unroll
    for (int mi = 0; mi < 2; ++mi)
#pragma unroll
        for (int nj = 0; nj < 4; ++nj) wmma::fill_fragment(facc[mi][nj], 0.0f);

    loadA(0); loadB(0);

    for (int it = 0; it < KIT; ++it) {
        // store current tile (split hi/lo)
        {
            uint4 hv, lv;
            split8(ra, hv, lv);
            *reinterpret_cast<uint4*>(sAh + lrow * LDA + lhalf * 8) = hv;
            *reinterpret_cast<uint4*>(sAl + lrow * LDA + lhalf * 8) = lv;
            split8(rb, hv, lv);
            *reinterpret_cast<uint4*>(sBh + kq * LDB + cq * 8) = hv;
            *reinterpret_cast<uint4*>(sBl + kq * LDB + cq * 8) = lv;
        }
        __syncthreads();
        if (it + 1 < KIT) { loadA((it + 1) * BK); loadB((it + 1) * BK); }

        wmma::fragment<wmma::matrix_a, 16, 16, 16, __nv_bfloat16, wmma::row_major> fa_h[2], fa_l[2];
#pragma unroll
        for (int mi = 0; mi < 2; ++mi) {
            wmma::load_matrix_sync(fa_h[mi], sAh + (wm * 32 + mi * 16) * LDA, LDA);
            wmma::load_matrix_sync(fa_l[mi], sAl + (wm * 32 + mi * 16) * LDA, LDA);
        }
#pragma unroll
        for (int nj = 0; nj < 4; ++nj) {
            wmma::fragment<wmma::matrix_b, 16, 16, 16, __nv_bfloat16, wmma::row_major> fb_h, fb_l;
            wmma::load_matrix_sync(fb_h, sBh + wn * 64 + nj * 16, LDB);
            wmma::load_matrix_sync(fb_l, sBl + wn * 64 + nj * 16, LDB);
#pragma unroll
            for (int mi = 0; mi < 2; ++mi) {
                wmma::mma_sync(facc[mi][nj], fa_h[mi], fb_h, facc[mi][nj]);
                wmma::mma_sync(facc[mi][nj], fa_h[mi], fb_l, facc[mi][nj]);
                wmma::mma_sync(facc[mi][nj], fa_l[mi], fb_h, facc[mi][nj]);
            }
        }
        __syncthreads();
    }

    // ---- epilogue: per-warp SMEM staging, predicated fp32 writes ----
    float* stg = reinterpret_cast<float*>(smem + wid * 1024);   // 16x16 f32 per warp
    const int r_loc = lane >> 1, c8 = (lane & 1) * 8;
#pragma unroll
    for (int mi = 0; mi < 2; ++mi) {
#pragma unroll
        for (int nj = 0; nj < 4; ++nj) {
            wmma::store_matrix_sync(stg, facc[mi][nj], 16, wmma::mem_row_major);
            __syncwarp();
            const int gr = rowBase + wm * 32 + mi * 16 + r_loc;
            if (gr < cnt) {
                float4 v0 = *reinterpret_cast<float4*>(stg + r_loc * 16 + c8);
                float4 v1 = *reinterpret_cast<float4*>(stg + r_loc * 16 + c8 + 4);
                const int col = nt * BN + wn * 64 + nj * 16 + c8;
                if (G1) {
                    v0 = make_float4(gelu_f(v0.x), gelu_f(v0.y), gelu_f(v0.z), gelu_f(v0.w));
                    v1 = make_float4(gelu_f(v1.x), gelu_f(v1.y), gelu_f(v1.z), gelu_f(v1.w));
                    float* dst = g_act + (size_t)(off + gr) * F_DIM + col;
                    *reinterpret_cast<float4*>(dst)     = v0;
                    *reinterpret_cast<float4*>(dst + 4) = v1;
                } else {
                    float* dst = g_y + (size_t)(off + gr) * H_DIM + col;
                    *reinterpret_cast<float4*>(dst)     = v0;
                    *reinterpret_cast<float4*>(dst + 4) = v1;
                }
            }
            __syncwarp();
        }
    }
}

// ============================ combine (verbatim round 1) ============================
__global__ __launch_bounds__(256) void combine(const float* __restrict__ probs,
                                               const float* __restrict__ resid,
                                               float* __restrict__ out) {
    const int t = blockIdx.x;
    const int h4 = threadIdx.x;
    float4 r = reinterpret_cast<const float4*>(resid + (size_t)t * H_DIM)[h4];
#pragma unroll
    for (int e = 0; e < NEXP; ++e) {
        int pos = g_pos[t * NEXP + e];
        if (pos >= 0) {
            float p = probs[t * NEXP + e];
            float4 v = reinterpret_cast<const float4*>(g_y + (size_t)(g_off[e] + pos) * H_DIM)[h4];
            r.x += p * v.x; r.y += p * v.y; r.z += p * v.z; r.w += p * v.w;
        }
    }
    reinterpret_cast<float4*>(out + (size_t)t * H_DIM)[h4] = r;
}

// ============================ launch ============================
extern "C" void kernel_launch(void* const* d_in, const int* in_sizes, int n_in,
                              void* d_out, int out_size) {
    const float* hidden = (const float*)d_in[0];
    const float* resid  = (const float*)d_in[1];
    const float* probs  = (const float*)d_in[2];
    const float* w1     = (const float*)d_in[4];
    const float* w2     = (const float*)d_in[5];
    float* out = (float*)d_out;

    build_lists<<<1, 32>>>(probs);
    gemm_wmma<true><<<dim3(F_DIM / BN, T_TOK / BM, NEXP), 256>>>(hidden, w1);   // X@W1, gelu -> g_act
    gemm_wmma<false><<<dim3(H_DIM / BN, T_TOK / BM, NEXP), 256>>>(hidden, w2);  // g_act@W2 -> g_y
    combine<<<T_TOK, 256>>>(probs, resid, out);
}

// round 10
// speedup vs baseline: 2.0473x; 1.3710x over previous
#include <cuda_runtime.h>
#include <cuda_bf16.h>
#include <mma.h>
#include <math.h>
#include <stdint.h>

using namespace nvcuda;

#define T_TOK 2048
#define H_DIM 1024
#define F_DIM 4096
#define NEXP  4

#define BM 128
#define BN 128
#define BK 16
#define LDA 24             // A tile ld (elems): 48 B rows
#define LDB 136            // B tile ld (elems): 272 B rows
#define STAGE_B 20992      // sAh 6144 | sAl 6144 | sBh 4352 | sBl 4352

__device__ __forceinline__ uint32_t pack_bf2(__nv_bfloat16 a, __nv_bfloat16 b) {
    __nv_bfloat162 t; t.x = a; t.y = b;
    return *reinterpret_cast<uint32_t*>(&t);
}
__device__ __forceinline__ float gelu_f(float v) {
    return 0.5f * v * (1.0f + erff(v * 0.70710678118654752440f));
}
// split 8 fp32 -> 8 bf16 hi + 8 bf16 lo, packed as uint4 each
__device__ __forceinline__ void split8(const float* r, uint4& hv, uint4& lv) {
    uint32_t h[4], l[4];
#pragma unroll
    for (int u = 0; u < 4; ++u) {
        float a = r[u * 2], b = r[u * 2 + 1];
        __nv_bfloat16 ha = __float2bfloat16_rn(a), hb = __float2bfloat16_rn(b);
        h[u] = pack_bf2(ha, hb);
        l[u] = pack_bf2(__float2bfloat16_rn(a - __bfloat162float(ha)),
                        __float2bfloat16_rn(b - __bfloat162float(hb)));
    }
    hv = make_uint4(h[0], h[1], h[2], h[3]);
    lv = make_uint4(l[0], l[1], l[2], l[3]);
}

// ============================ scratch ============================
__device__ float g_act[(size_t)T_TOK * 2 * F_DIM];   // compact fp32 [4096][F]
__device__ float g_y[(size_t)T_TOK * 2 * H_DIM];     // compact fp32 [4096][H]
__device__ int g_cnt[NEXP];
__device__ int g_off[NEXP + 1];
__device__ int g_idx[NEXP * T_TOK];
__device__ int g_pos[T_TOK * NEXP];

// ============================ routing (proven) ============================
__global__ void build_lists(const float* __restrict__ probs) {
    int e = threadIdx.x;
    if (e < NEXP) {
        int c = 0;
        for (int t = 0; t < T_TOK; ++t) {
            float p = probs[t * NEXP + e];
            if (p > 0.0f) {
                g_idx[e * T_TOK + c] = t;
                g_pos[t * NEXP + e]  = c;
                ++c;
            } else {
                g_pos[t * NEXP + e] = -1;
            }
        }
        g_cnt[e] = c;
    }
    __syncthreads();
    if (e == 0) {
        int acc = 0;
        for (int i = 0; i < NEXP; ++i) { g_off[i] = acc; acc += g_cnt[i]; }
        g_off[NEXP] = acc;
    }
}

// ============================ wmma bf16x3 GEMM, double-buffered ============================
// 8 warps = 4(m) x 2(n); warp tile 32m x 64n; wmma 16x16x16; one sync per k-iter.
template <bool G1>
__global__ __launch_bounds__(256, 2) void gemm_wmma(const float* __restrict__ X,
                                                    const float* __restrict__ W) {
    __shared__ __align__(16) char smem[2 * STAGE_B];

    const int e = blockIdx.z, mt = blockIdx.y, nt = blockIdx.x;
    const int cnt = g_cnt[e];
    const int rowBase = mt * BM;
    if (rowBase >= cnt) return;
    const int off = g_off[e];
    constexpr int K = G1 ? H_DIM : F_DIM;
    constexpr int N = G1 ? F_DIM : H_DIM;
    constexpr int KIT = K / BK;

    const int tid = threadIdx.x, lane = tid & 31, wid = tid >> 5;
    const int wm = wid & 3, wn = wid >> 2;

    // ---- A: 2 threads per row, 8 fp32 each ----
    const int lrow = tid >> 1, lhalf = tid & 1;
    const float* Asrc;
    {
        int gr = rowBase + lrow;
        int cr = gr < cnt ? gr : cnt - 1;          // clamp; masked at epilogue
        if (G1) Asrc = X + (size_t)g_idx[e * T_TOK + cr] * H_DIM;
        else    Asrc = g_act + (size_t)(off + cr) * F_DIM;
    }
    // ---- B: 16 threads per k-row, 8 fp32 each; W is [e][K][N] row-major ----
    const int kq = tid >> 4, cq = tid & 15;
    const float* Bsrc = W + (size_t)e * K * N + nt * BN + cq * 8;

    float ra[8], rb[8];
    auto loadA = [&](int k0) {
        float4 v0 = *reinterpret_cast<const float4*>(Asrc + k0 + lhalf * 8);
        float4 v1 = *reinterpret_cast<const float4*>(Asrc + k0 + lhalf * 8 + 4);
        ra[0] = v0.x; ra[1] = v0.y; ra[2] = v0.z; ra[3] = v0.w;
        ra[4] = v1.x; ra[5] = v1.y; ra[6] = v1.z; ra[7] = v1.w;
    };
    auto loadB = [&](int k0) {
        const float* p = Bsrc + (size_t)(k0 + kq) * N;
        float4 v0 = *reinterpret_cast<const float4*>(p);
        float4 v1 = *reinterpret_cast<const float4*>(p + 4);
        rb[0] = v0.x; rb[1] = v0.y; rb[2] = v0.z; rb[3] = v0.w;
        rb[4] = v1.x; rb[5] = v1.y; rb[6] = v1.z; rb[7] = v1.w;
    };
    auto storeTile = [&](int s) {
        char* bs = smem + s * STAGE_B;
        uint4 hv, lv;
        split8(ra, hv, lv);
        *reinterpret_cast<uint4*>(bs + (lrow * LDA + lhalf * 8) * 2)        = hv;
        *reinterpret_cast<uint4*>(bs + 6144 + (lrow * LDA + lhalf * 8) * 2) = lv;
        split8(rb, hv, lv);
        *reinterpret_cast<uint4*>(bs + 12288 + (kq * LDB + cq * 8) * 2)     = hv;
        *reinterpret_cast<uint4*>(bs + 16640 + (kq * LDB + cq * 8) * 2)     = lv;
    };

    wmma::fragment<wmma::accumulator, 16, 16, 16, float> facc[2][4];
#pragma unroll
    for (int mi = 0; mi < 2; ++mi)
#pragma unroll
        for (int nj = 0; nj < 4; ++nj) wmma::fill_fragment(facc[mi][nj], 0.0f);

    // ---- prologue: fill stage 0, prefetch k=1 into regs ----
    loadA(0); loadB(0);
    storeTile(0);
    loadA(BK); loadB(BK);
    __syncthreads();

    // ---- mainloop: one sync per iter; store next stage + prefetch overlap compute ----
    for (int it = 0; it < KIT; ++it) {
        if (it + 1 < KIT) storeTile((it + 1) & 1);
        if (it + 2 < KIT) { loadA((it + 2) * BK); loadB((it + 2) * BK); }

        const char* bs = smem + (it & 1) * STAGE_B;
        const __nv_bfloat16* sAh = reinterpret_cast<const __nv_bfloat16*>(bs);
        const __nv_bfloat16* sAl = reinterpret_cast<const __nv_bfloat16*>(bs + 6144);
        const __nv_bfloat16* sBh = reinterpret_cast<const __nv_bfloat16*>(bs + 12288);
        const __nv_bfloat16* sBl = reinterpret_cast<const __nv_bfloat16*>(bs + 16640);

        wmma::fragment<wmma::matrix_a, 16, 16, 16, __nv_bfloat16, wmma::row_major> fa_h[2], fa_l[2];
#pragma unroll
        for (int mi = 0; mi < 2; ++mi) {
            wmma::load_matrix_sync(fa_h[mi], sAh + (wm * 32 + mi * 16) * LDA, LDA);
            wmma::load_matrix_sync(fa_l[mi], sAl + (wm * 32 + mi * 16) * LDA, LDA);
        }
#pragma unroll
        for (int nj = 0; nj < 4; ++nj) {
            wmma::fragment<wmma::matrix_b, 16, 16, 16, __nv_bfloat16, wmma::row_major> fb_h, fb_l;
            wmma::load_matrix_sync(fb_h, sBh + wn * 64 + nj * 16, LDB);
            wmma::load_matrix_sync(fb_l, sBl + wn * 64 + nj * 16, LDB);
#pragma unroll
            for (int mi = 0; mi < 2; ++mi) {
                wmma::mma_sync(facc[mi][nj], fa_h[mi], fb_h, facc[mi][nj]);
                wmma::mma_sync(facc[mi][nj], fa_h[mi], fb_l, facc[mi][nj]);
                wmma::mma_sync(facc[mi][nj], fa_l[mi], fb_h, facc[mi][nj]);
            }
        }
        __syncthreads();
    }

    // ---- epilogue: per-warp SMEM staging, predicated fp32 writes ----
    float* stg = reinterpret_cast<float*>(smem + wid * 1024);   // 16x16 f32 per warp
    const int r_loc = lane >> 1, c8 = (lane & 1) * 8;
#pragma unroll
    for (int mi = 0; mi < 2; ++mi) {
#pragma unroll
        for (int nj = 0; nj < 4; ++nj) {
            wmma::store_matrix_sync(stg, facc[mi][nj], 16, wmma::mem_row_major);
            __syncwarp();
            const int gr = rowBase + wm * 32 + mi * 16 + r_loc;
            if (gr < cnt) {
                float4 v0 = *reinterpret_cast<float4*>(stg + r_loc * 16 + c8);
                float4 v1 = *reinterpret_cast<float4*>(stg + r_loc * 16 + c8 + 4);
                const int col = nt * BN + wn * 64 + nj * 16 + c8;
                if (G1) {
                    v0 = make_float4(gelu_f(v0.x), gelu_f(v0.y), gelu_f(v0.z), gelu_f(v0.w));
                    v1 = make_float4(gelu_f(v1.x), gelu_f(v1.y), gelu_f(v1.z), gelu_f(v1.w));
                    float* dst = g_act + (size_t)(off + gr) * F_DIM + col;
                    *reinterpret_cast<float4*>(dst)     = v0;
                    *reinterpret_cast<float4*>(dst + 4) = v1;
                } else {
                    float* dst = g_y + (size_t)(off + gr) * H_DIM + col;
                    *reinterpret_cast<float4*>(dst)     = v0;
                    *reinterpret_cast<float4*>(dst + 4) = v1;
                }
            }
            __syncwarp();
        }
    }
}

// ============================ combine (proven) ============================
__global__ __launch_bounds__(256) void combine(const float* __restrict__ probs,
                                               const float* __restrict__ resid,
                                               float* __restrict__ out) {
    const int t = blockIdx.x;
    const int h4 = threadIdx.x;
    float4 r = reinterpret_cast<const float4*>(resid + (size_t)t * H_DIM)[h4];
#pragma unroll
    for (int e = 0; e < NEXP; ++e) {
        int pos = g_pos[t * NEXP + e];
        if (pos >= 0) {
            float p = probs[t * NEXP + e];
            float4 v = reinterpret_cast<const float4*>(g_y + (size_t)(g_off[e] + pos) * H_DIM)[h4];
            r.x += p * v.x; r.y += p * v.y; r.z += p * v.z; r.w += p * v.w;
        }
    }
    reinterpret_cast<float4*>(out + (size_t)t * H_DIM)[h4] = r;
}

// ============================ launch ============================
extern "C" void kernel_launch(void* const* d_in, const int* in_sizes, int n_in,
                              void* d_out, int out_size) {
    const float* hidden = (const float*)d_in[0];
    const float* resid  = (const float*)d_in[1];
    const float* probs  = (const float*)d_in[2];
    const float* w1     = (const float*)d_in[4];
    const float* w2     = (const float*)d_in[5];
    float* out = (float*)d_out;

    build_lists<<<1, 32>>>(probs);
    gemm_wmma<true><<<dim3(F_DIM / BN, T_TOK / BM, NEXP), 256>>>(hidden, w1);   // X@W1, gelu -> g_act
    gemm_wmma<false><<<dim3(H_DIM / BN, T_TOK / BM, NEXP), 256>>>(hidden, w2);  // g_act@W2 -> g_y
    combine<<<T_TOK, 256>>>(probs, resid, out);
}